// round 1
// baseline (speedup 1.0000x reference)
#include <cuda_runtime.h>
#include <cuda_bf16.h>
#include <cstdint>

// Problem constants: B=4, N=512, F=H=K=64
#define NN 512
#define BN 2048           // B*N
#define FD 64
#define EPSV 1e-14f

// ---------------- scratch (no cudaMalloc allowed) ----------------
__device__ float g_pj_ew[BN * FD];   // [n][k]   (n = b*512 + j)
__device__ float g_pi_ew[BN * FD];   // [n][k]
__device__ float g_pjesT[BN * FD];   // [b][h][j] transposed: ((b*64+h)*512 + j)
__device__ float g_pi_es[BN * FD];   // [n][h]
__device__ float g_pj_sa[BN];
__device__ float g_pi_sa[BN];

__device__ __forceinline__ float silu_f(float v) {
    return __fdividef(v, 1.0f + __expf(-v));
}
__device__ __forceinline__ float tanh_fast(float v) {
    v = fminf(fmaxf(v, -15.0f), 15.0f);
    float e = __expf(2.0f * v);
    return __fdividef(e - 1.0f, e + 1.0f);
}

// ---------------- kernel A: node-level projections ----------------
__global__ void sake_pre(const float* __restrict__ h,
                         const float* __restrict__ W_ew,
                         const float* __restrict__ W_es,
                         const float* __restrict__ W_sa) {
    int n = blockIdx.x;          // node id = b*512 + j
    int k = threadIdx.x;         // 0..63
    __shared__ float sh[FD];
    __shared__ float sp1[FD], sp2[FD];
    sh[k] = h[n * FD + k];
    __syncthreads();
    float a_jew = 0.f, a_iew = 0.f, a_jes = 0.f, a_ies = 0.f;
#pragma unroll 8
    for (int f = 0; f < FD; f++) {
        float hf = sh[f];
        a_jew = fmaf(hf, W_ew[f * FD + k], a_jew);
        a_iew = fmaf(hf, W_ew[(FD + f) * FD + k], a_iew);
        a_jes = fmaf(hf, W_es[(1 + f) * FD + k], a_jes);          // W_es rows 1..64
        a_ies = fmaf(hf, W_es[(1 + FD + f) * FD + k], a_ies);     // W_es rows 65..128
    }
    g_pj_ew[n * FD + k] = a_jew;
    g_pi_ew[n * FD + k] = a_iew;
    int b = n >> 9, j = n & 511;
    g_pjesT[(b * FD + k) * NN + j] = a_jes;
    g_pi_es[n * FD + k] = a_ies;
    sp1[k] = sh[k] * W_sa[k];
    sp2[k] = sh[k] * W_sa[FD + k];
    __syncthreads();
    if (k == 0) { float s = 0.f; for (int f = 0; f < FD; f++) s += sp1[f]; g_pj_sa[n] = s; }
    if (k == 1) { float s = 0.f; for (int f = 0; f < FD; f++) s += sp2[f]; g_pi_sa[n] = s; }
}

// ---------------- kernel B: fused pairwise main ----------------
__global__ __launch_bounds__(256) void sake_main(
    const float* __restrict__ h, const float* __restrict__ x,
    const float* __restrict__ b_ew, const float* __restrict__ W_es,
    const float* __restrict__ b_es, const float* __restrict__ W_c1,
    const float* __restrict__ b_c1, const float* __restrict__ W_c2,
    const float* __restrict__ b_c2, const float* __restrict__ W_n,
    const float* __restrict__ b_n, float* __restrict__ out)
{
    const int n_i = blockIdx.x;        // b*512 + i
    const int b = n_i >> 9;
    const int t = threadIdx.x;
    const int warp = t >> 5, lane = t & 31;

    __shared__ __align__(16) float s_Wc1T[FD * FD];   // [m][h]
    __shared__ float s_xmx[NN * 3];
    __shared__ float s_v[NN * 3];
    __shared__ float s_filt[NN];
    __shared__ float s_sw[NN];                        // sem * exp(norm)
    __shared__ float s_piew[FD], s_pies[FD], s_wes0[FD], s_bc1[FD], s_wc2[FD];
    __shared__ float s_attp[4][FD][3];
    __shared__ float s_aggp[8][FD];
    __shared__ float s_agg[FD], s_attn[FD];
    __shared__ float s_xp[8][3];
    __shared__ float s_red[8];
    __shared__ float s_scal[1];

    // ---- setup ----
    for (int idx = t; idx < FD * FD; idx += 256) {
        int hh = idx >> 6, m = idx & 63;
        s_Wc1T[m * FD + hh] = W_c1[idx];              // transpose: [m][h]
    }
    if (t < FD) {
        s_piew[t] = g_pi_ew[n_i * FD + t] + b_ew[t];
        s_pies[t] = g_pi_es[n_i * FD + t] + b_es[t];
        s_wes0[t] = W_es[t];                          // row 0 of W_es
        s_bc1[t]  = b_c1[t];
        s_wc2[t]  = W_c2[t];
    }
    for (int idx = t; idx < 8 * FD; idx += 256) ((float*)s_aggp)[idx] = 0.f;

    const float xi0 = x[n_i * 3 + 0], xi1 = x[n_i * 3 + 1], xi2 = x[n_i * 3 + 2];
    const float pi_sa_v = g_pi_sa[n_i];
    const float bc2v = b_c2[0];

    // ---- pass 1: per-j geometry + softmax numerators ----
    float esum = 0.f;
    for (int j = t; j < NN; j += 256) {
        float dx = x[(b * NN + j) * 3 + 0] - xi0;
        float dy = x[(b * NN + j) * 3 + 1] - xi1;
        float dz = x[(b * NN + j) * 3 + 2] - xi2;
        float d2 = dx * dx + dy * dy + dz * dz;
        float nrm = sqrtf(d2 + EPSV);
        s_xmx[j * 3 + 0] = dx; s_xmx[j * 3 + 1] = dy; s_xmx[j * 3 + 2] = dz;
        float inv2 = 1.0f / (nrm * nrm + EPSV);
        s_v[j * 3 + 0] = dx * inv2; s_v[j * 3 + 1] = dy * inv2; s_v[j * 3 + 2] = dz * inv2;
        s_filt[j] = 1.0f / (nrm + 0.1f);
        float en = __expf(nrm);
        esum += en;
        float sem = g_pj_sa[b * NN + j] + pi_sa_v;
        sem = (sem > 0.f) ? sem : 0.01f * sem;        // leaky_relu(0.01)
        s_sw[j] = sem * en;
    }
#pragma unroll
    for (int o = 16; o; o >>= 1) esum += __shfl_xor_sync(0xffffffffu, esum, o);
    if (lane == 0) s_red[warp] = esum;
    __syncthreads();
    if (t == 0) {
        float s = 0.f;
#pragma unroll
        for (int w = 0; w < 8; w++) s += s_red[w];
        s_scal[0] = 1.0f / s;
    }
    __syncthreads();

    // ---- pass 2: att_sum einsum  (att[k][c] = sum_j tanh(...)*v[j][c]) ----
    {
        int k = t & 63, jb = t >> 6;                   // 4 j-blocks of 128
        float base = s_piew[k];
        const float* pjew = g_pj_ew + (size_t)(b * NN) * FD + k;
        float a0 = 0.f, a1 = 0.f, a2 = 0.f;
        int j0 = jb * 128;
#pragma unroll 4
        for (int jj = 0; jj < 128; jj++) {
            int j = j0 + jj;
            float e = tanh_fast(pjew[(size_t)j * FD] + base);
            a0 = fmaf(e, s_v[j * 3 + 0], a0);
            a1 = fmaf(e, s_v[j * 3 + 1], a1);
            a2 = fmaf(e, s_v[j * 3 + 2], a2);
        }
        s_attp[jb][k][0] = a0; s_attp[jb][k][1] = a1; s_attp[jb][k][2] = a2;
    }

    // ---- pass 3: main per-pair loop (thread-per-j) ----
    const float inv_sum = s_scal[0];
    float xacc0 = 0.f, xacc1 = 0.f, xacc2 = 0.f;
    float agg0 = 0.f, agg1 = 0.f;                      // this lane's h=lane, h=lane+32

    for (int jt = 0; jt < 2; jt++) {
        int j = jt * 256 + t;
        float filt = s_filt[j];
        const float* pjes = g_pjesT + (size_t)(b * FD) * NN + j;   // + h*512

        float he[FD];
#pragma unroll
        for (int hh = 0; hh < FD; hh++) {
            float pre = fmaf(filt, s_wes0[hh], pjes[(size_t)hh * NN] + s_pies[hh]);
            he[hh] = silu_f(pre);
        }

        // h_e_agg contribution: reduce w*he[h] across lanes (32 j's per warp)
        float w = s_sw[j] * inv_sum;
#pragma unroll
        for (int hh = 0; hh < FD; hh++) {
            float v = w * he[hh];
#pragma unroll
            for (int o = 16; o; o >>= 1) v += __shfl_xor_sync(0xffffffffu, v, o);
            if (hh < 32) { if (lane == hh) agg0 += v; }
            else         { if (lane == hh - 32) agg1 += v; }
        }

        // matvec: coord = silu(he @ W_c1 + b_c1) @ W_c2 + b_c2
        float csum = 0.f;
        for (int m = 0; m < FD; m++) {
            float acc = s_bc1[m];
            const float4* wrow = (const float4*)(s_Wc1T + m * FD);
#pragma unroll
            for (int hq = 0; hq < 16; hq++) {
                float4 wv = wrow[hq];
                acc = fmaf(he[4 * hq + 0], wv.x, acc);
                acc = fmaf(he[4 * hq + 1], wv.y, acc);
                acc = fmaf(he[4 * hq + 2], wv.z, acc);
                acc = fmaf(he[4 * hq + 3], wv.w, acc);
            }
            float u = silu_f(acc);
            csum = fmaf(u, s_wc2[m], csum);
        }
        float coord = csum + bc2v;
        xacc0 = fmaf(s_xmx[j * 3 + 0], coord, xacc0);
        xacc1 = fmaf(s_xmx[j * 3 + 1], coord, xacc1);
        xacc2 = fmaf(s_xmx[j * 3 + 2], coord, xacc2);
    }

    // warp-level partials -> shared
#pragma unroll
    for (int o = 16; o; o >>= 1) {
        xacc0 += __shfl_xor_sync(0xffffffffu, xacc0, o);
        xacc1 += __shfl_xor_sync(0xffffffffu, xacc1, o);
        xacc2 += __shfl_xor_sync(0xffffffffu, xacc2, o);
    }
    if (lane == 0) { s_xp[warp][0] = xacc0; s_xp[warp][1] = xacc1; s_xp[warp][2] = xacc2; }
    s_aggp[warp][lane]      = agg0;
    s_aggp[warp][lane + 32] = agg1;
    __syncthreads();

    // ---- finalize att_norm and h_e_agg ----
    if (t < FD) {
        float a0 = s_attp[0][t][0] + s_attp[1][t][0] + s_attp[2][t][0] + s_attp[3][t][0];
        float a1 = s_attp[0][t][1] + s_attp[1][t][1] + s_attp[2][t][1] + s_attp[3][t][1];
        float a2 = s_attp[0][t][2] + s_attp[1][t][2] + s_attp[2][t][2] + s_attp[3][t][2];
        s_attn[t] = sqrtf(a0 * a0 + a1 * a1 + a2 * a2 + EPSV);
        float ag = 0.f;
#pragma unroll
        for (int w2 = 0; w2 < 8; w2++) ag += s_aggp[w2][t];
        s_agg[t] = ag;
    }
    __syncthreads();

    // ---- h_new = concat(h, agg, attn) @ W_n + b_n ----
    if (t < FD) {
        int m = t;
        float acc = b_n[m];
        const float* hi = h + (size_t)n_i * FD;
#pragma unroll 8
        for (int f = 0; f < FD; f++)  acc = fmaf(hi[f],      W_n[f * FD + m], acc);
#pragma unroll 8
        for (int f = 0; f < FD; f++)  acc = fmaf(s_agg[f],   W_n[(FD + f) * FD + m], acc);
#pragma unroll 8
        for (int f = 0; f < FD; f++)  acc = fmaf(s_attn[f],  W_n[(2 * FD + f) * FD + m], acc);
        out[(size_t)n_i * FD + m] = acc;
    }
    if (t >= 64 && t < 67) {
        int c = t - 64;
        float xs = 0.f;
#pragma unroll
        for (int w2 = 0; w2 < 8; w2++) xs += s_xp[w2][c];
        out[(size_t)BN * FD + n_i * 3 + c] = x[n_i * 3 + c] + xs;
    }
}

extern "C" void kernel_launch(void* const* d_in, const int* in_sizes, int n_in,
                              void* d_out, int out_size) {
    const float* h    = (const float*)d_in[0];
    const float* x    = (const float*)d_in[1];
    const float* W_ew = (const float*)d_in[2];
    const float* b_ew = (const float*)d_in[3];
    const float* W_sa = (const float*)d_in[4];
    const float* W_es = (const float*)d_in[5];
    const float* b_es = (const float*)d_in[6];
    const float* W_c1 = (const float*)d_in[7];
    const float* b_c1 = (const float*)d_in[8];
    const float* W_c2 = (const float*)d_in[9];
    const float* b_c2 = (const float*)d_in[10];
    const float* W_n  = (const float*)d_in[11];
    const float* b_n  = (const float*)d_in[12];
    float* out = (float*)d_out;

    sake_pre<<<BN, 64>>>(h, W_ew, W_es, W_sa);
    sake_main<<<BN, 256>>>(h, x, b_ew, W_es, b_es, W_c1, b_c1, W_c2, b_c2, W_n, b_n, out);
}

// round 2
// speedup vs baseline: 1.6799x; 1.6799x over previous
#include <cuda_runtime.h>
#include <cuda_bf16.h>
#include <cstdint>

#define NN 512
#define BN 2048
#define FD 64
#define EPSV 1e-14f

typedef unsigned long long ull;

// ---------------- scratch ----------------
__device__ float g_pj_ew[BN * FD];
__device__ float g_pi_ew[BN * FD];
__device__ float g_pjesT[BN * FD];   // [b][h][j]
__device__ float g_pi_es[BN * FD];
__device__ float g_pj_sa[BN];
__device__ float g_pi_sa[BN];

__device__ __forceinline__ float tanh_hw(float v) {
    float r; asm("tanh.approx.f32 %0, %1;" : "=f"(r) : "f"(v)); return r;
}
__device__ __forceinline__ float silu_hw(float v) {
    float m = 0.5f * v;
    return fmaf(m, tanh_hw(m), m);
}
__device__ __forceinline__ float tanh_fast(float v) {
    v = fminf(fmaxf(v, -15.0f), 15.0f);
    float e = __expf(2.0f * v);
    return __fdividef(e - 1.0f, e + 1.0f);
}
__device__ __forceinline__ ull pack2(float lo, float hi) {
    ull r; asm("mov.b64 %0, {%1, %2};" : "=l"(r) : "f"(lo), "f"(hi)); return r;
}
__device__ __forceinline__ void unpack2(ull v, float& lo, float& hi) {
    asm("mov.b64 {%0, %1}, %2;" : "=f"(lo), "=f"(hi) : "l"(v));
}
__device__ __forceinline__ void fma2(ull& d, ull a, ull b) {
    asm("fma.rn.f32x2 %0, %1, %2, %0;" : "+l"(d) : "l"(a), "l"(b));
}
__device__ __forceinline__ ull add2(ull a, ull b) {
    ull r; asm("add.rn.f32x2 %0, %1, %2;" : "=l"(r) : "l"(a), "l"(b)); return r;
}
__device__ __forceinline__ ull mul2(ull a, ull b) {
    ull r; asm("mul.rn.f32x2 %0, %1, %2;" : "=l"(r) : "l"(a), "l"(b)); return r;
}
__device__ __forceinline__ void lds2(const float* p, ull& a, ull& b) {
    unsigned ad = (unsigned)__cvta_generic_to_shared(p);
    asm("ld.shared.v2.u64 {%0, %1}, [%2];" : "=l"(a), "=l"(b) : "r"(ad));
}

// ---------------- kernel A: node-level projections ----------------
__global__ void sake_pre(const float* __restrict__ h,
                         const float* __restrict__ W_ew,
                         const float* __restrict__ W_es,
                         const float* __restrict__ W_sa) {
    int n = blockIdx.x;
    int k = threadIdx.x;
    __shared__ float sh[FD];
    __shared__ float sp1[FD], sp2[FD];
    sh[k] = h[n * FD + k];
    __syncthreads();
    float a_jew = 0.f, a_iew = 0.f, a_jes = 0.f, a_ies = 0.f;
#pragma unroll 8
    for (int f = 0; f < FD; f++) {
        float hf = sh[f];
        a_jew = fmaf(hf, W_ew[f * FD + k], a_jew);
        a_iew = fmaf(hf, W_ew[(FD + f) * FD + k], a_iew);
        a_jes = fmaf(hf, W_es[(1 + f) * FD + k], a_jes);
        a_ies = fmaf(hf, W_es[(1 + FD + f) * FD + k], a_ies);
    }
    g_pj_ew[n * FD + k] = a_jew;
    g_pi_ew[n * FD + k] = a_iew;
    int b = n >> 9, j = n & 511;
    g_pjesT[(b * FD + k) * NN + j] = a_jes;
    g_pi_es[n * FD + k] = a_ies;
    sp1[k] = sh[k] * W_sa[k];
    sp2[k] = sh[k] * W_sa[FD + k];
    __syncthreads();
    if (k == 0) { float s = 0.f; for (int f = 0; f < FD; f++) s += sp1[f]; g_pj_sa[n] = s; }
    if (k == 1) { float s = 0.f; for (int f = 0; f < FD; f++) s += sp2[f]; g_pi_sa[n] = s; }
}

// ---------------- kernel B: fused pairwise main ----------------
__global__ __launch_bounds__(256, 2) void sake_main(
    const float* __restrict__ h, const float* __restrict__ x,
    const float* __restrict__ b_ew, const float* __restrict__ W_es,
    const float* __restrict__ b_es, const float* __restrict__ W_c1,
    const float* __restrict__ b_c1, const float* __restrict__ W_c2,
    const float* __restrict__ b_c2, const float* __restrict__ W_n,
    const float* __restrict__ b_n, float* __restrict__ out)
{
    const int n_i = blockIdx.x;
    const int b = n_i >> 9;
    const int t = threadIdx.x;
    const int warp = t >> 5, lane = t & 31;

    __shared__ __align__(16) float s_Wc1T[FD * FD];   // [m][h]
    __shared__ float s_xmx[NN * 3];
    __shared__ float s_v[NN * 3];
    __shared__ float s_filt[NN];
    __shared__ float s_sw[NN];
    __shared__ float s_piew[FD], s_pies[FD], s_wes0[FD], s_bc1[FD], s_wc2[FD];
    __shared__ float s_attp[4][FD][3];
    __shared__ float s_aggp[8][FD];
    __shared__ float s_agg[FD], s_attn[FD];
    __shared__ float s_xp[8][3];
    __shared__ float s_red[8];
    __shared__ float s_scal[1];

    // ---- setup ----
    for (int idx = t; idx < FD * FD; idx += 256) {
        int hh = idx >> 6, m = idx & 63;
        s_Wc1T[m * FD + hh] = W_c1[idx];
    }
    if (t < FD) {
        s_piew[t] = g_pi_ew[n_i * FD + t] + b_ew[t];
        s_pies[t] = g_pi_es[n_i * FD + t] + b_es[t];
        s_wes0[t] = W_es[t];
        s_bc1[t]  = b_c1[t];
        s_wc2[t]  = W_c2[t];
    }

    const float xi0 = x[n_i * 3 + 0], xi1 = x[n_i * 3 + 1], xi2 = x[n_i * 3 + 2];
    const float pi_sa_v = g_pi_sa[n_i];
    const float bc2v = b_c2[0];

    // ---- pass 1: per-j geometry + softmax numerators ----
    float esum = 0.f;
    for (int j = t; j < NN; j += 256) {
        float dx = x[(b * NN + j) * 3 + 0] - xi0;
        float dy = x[(b * NN + j) * 3 + 1] - xi1;
        float dz = x[(b * NN + j) * 3 + 2] - xi2;
        float d2 = dx * dx + dy * dy + dz * dz;
        float nrm = sqrtf(d2 + EPSV);
        s_xmx[j * 3 + 0] = dx; s_xmx[j * 3 + 1] = dy; s_xmx[j * 3 + 2] = dz;
        float inv2 = 1.0f / (nrm * nrm + EPSV);
        s_v[j * 3 + 0] = dx * inv2; s_v[j * 3 + 1] = dy * inv2; s_v[j * 3 + 2] = dz * inv2;
        s_filt[j] = 1.0f / (nrm + 0.1f);
        float en = __expf(nrm);
        esum += en;
        float sem = g_pj_sa[b * NN + j] + pi_sa_v;
        sem = (sem > 0.f) ? sem : 0.01f * sem;
        s_sw[j] = sem * en;
    }
#pragma unroll
    for (int o = 16; o; o >>= 1) esum += __shfl_xor_sync(0xffffffffu, esum, o);
    if (lane == 0) s_red[warp] = esum;
    __syncthreads();
    if (t == 0) {
        float s = 0.f;
#pragma unroll
        for (int w = 0; w < 8; w++) s += s_red[w];
        s_scal[0] = 1.0f / s;
    }
    __syncthreads();

    // ---- pass 2: att_sum einsum ----
    {
        int k = t & 63, jb = t >> 6;
        float base = s_piew[k];
        const float* pjew = g_pj_ew + (size_t)(b * NN) * FD + k;
        float a0 = 0.f, a1 = 0.f, a2 = 0.f;
        int j0 = jb * 128;
#pragma unroll 4
        for (int jj = 0; jj < 128; jj++) {
            int j = j0 + jj;
            float e = tanh_fast(pjew[(size_t)j * FD] + base);
            a0 = fmaf(e, s_v[j * 3 + 0], a0);
            a1 = fmaf(e, s_v[j * 3 + 1], a1);
            a2 = fmaf(e, s_v[j * 3 + 2], a2);
        }
        s_attp[jb][k][0] = a0; s_attp[jb][k][1] = a1; s_attp[jb][k][2] = a2;
    }

    // ---- pass 3: main per-pair loop (thread-per-j) ----
    const float inv_sum = s_scal[0];
    float xacc0 = 0.f, xacc1 = 0.f, xacc2 = 0.f;
    ull aggacc = 0ull;   // packed (0.0f, 0.0f)

    for (int jt = 0; jt < 2; jt++) {
        const int j = jt * 256 + t;
        const float filt = s_filt[j];
        const float* pjes = g_pjesT + (size_t)(b * FD) * NN + j;

        ull hep[32];
#pragma unroll
        for (int hh = 0; hh < FD; hh += 2) {
            float p0 = pjes[(size_t)hh * NN]       + fmaf(filt, s_wes0[hh],     s_pies[hh]);
            float p1 = pjes[(size_t)(hh + 1) * NN] + fmaf(filt, s_wes0[hh + 1], s_pies[hh + 1]);
            hep[hh >> 1] = pack2(silu_hw(p0), silu_hw(p1));
        }

        // matvec: coord = silu(he @ W_c1 + b_c1) @ W_c2 + b_c2  (packed f32x2)
        float csum = 0.f;
#pragma unroll 4
        for (int m = 0; m < FD; m++) {
            const float* wrow = s_Wc1T + m * FD;
            ull acc0 = 0ull, acc1 = 0ull;
#pragma unroll
            for (int q = 0; q < 16; q++) {
                ull w0, w1;
                lds2(wrow + q * 4, w0, w1);
                fma2(acc0, hep[2 * q],     w0);
                fma2(acc1, hep[2 * q + 1], w1);
            }
            float a0, a1;
            unpack2(add2(acc0, acc1), a0, a1);
            float u = silu_hw(a0 + a1 + s_bc1[m]);
            csum = fmaf(u, s_wc2[m], csum);
        }
        float coord = csum + bc2v;
        xacc0 = fmaf(s_xmx[j * 3 + 0], coord, xacc0);
        xacc1 = fmaf(s_xmx[j * 3 + 1], coord, xacc1);
        xacc2 = fmaf(s_xmx[j * 3 + 2], coord, xacc2);

        // weighted tree-reduce of he across lanes (destructive on hep)
        float w = s_sw[j] * inv_sum;
        ull wp = pack2(w, w);
#pragma unroll
        for (int k2 = 0; k2 < 32; k2++) hep[k2] = mul2(hep[k2], wp);
#pragma unroll
        for (int p = 0; p < 5; p++) {
            const int L = 32 >> p;
            const bool hi = (lane >> p) & 1;
#pragma unroll
            for (int k2 = 0; k2 < 16; k2++) {
                if (k2 < (L >> 1)) {
                    ull keep = hi ? hep[k2 + (L >> 1)] : hep[k2];
                    ull send = hi ? hep[k2] : hep[k2 + (L >> 1)];
                    ull rec = __shfl_xor_sync(0xffffffffu, send, 1 << p);
                    hep[k2] = add2(keep, rec);
                }
            }
        }
        aggacc = add2(aggacc, hep[0]);
    }

    // lane -> h mapping from the tree reduce (bit-reversal)
    {
        int kk = ((lane & 1) << 4) | (((lane >> 1) & 1) << 3) | (((lane >> 2) & 1) << 2)
               | (((lane >> 3) & 1) << 1) | ((lane >> 4) & 1);
        float glo, ghi;
        unpack2(aggacc, glo, ghi);
        s_aggp[warp][2 * kk]     = glo;
        s_aggp[warp][2 * kk + 1] = ghi;
    }
#pragma unroll
    for (int o = 16; o; o >>= 1) {
        xacc0 += __shfl_xor_sync(0xffffffffu, xacc0, o);
        xacc1 += __shfl_xor_sync(0xffffffffu, xacc1, o);
        xacc2 += __shfl_xor_sync(0xffffffffu, xacc2, o);
    }
    if (lane == 0) { s_xp[warp][0] = xacc0; s_xp[warp][1] = xacc1; s_xp[warp][2] = xacc2; }
    __syncthreads();

    // ---- finalize att_norm and h_e_agg ----
    if (t < FD) {
        float a0 = s_attp[0][t][0] + s_attp[1][t][0] + s_attp[2][t][0] + s_attp[3][t][0];
        float a1 = s_attp[0][t][1] + s_attp[1][t][1] + s_attp[2][t][1] + s_attp[3][t][1];
        float a2 = s_attp[0][t][2] + s_attp[1][t][2] + s_attp[2][t][2] + s_attp[3][t][2];
        s_attn[t] = sqrtf(a0 * a0 + a1 * a1 + a2 * a2 + EPSV);
        float ag = 0.f;
#pragma unroll
        for (int w2 = 0; w2 < 8; w2++) ag += s_aggp[w2][t];
        s_agg[t] = ag;
    }
    __syncthreads();

    // ---- h_new = concat(h, agg, attn) @ W_n + b_n ----
    if (t < FD) {
        int m = t;
        float acc = b_n[m];
        const float* hi2 = h + (size_t)n_i * FD;
#pragma unroll 8
        for (int f = 0; f < FD; f++)  acc = fmaf(hi2[f],     W_n[f * FD + m], acc);
#pragma unroll 8
        for (int f = 0; f < FD; f++)  acc = fmaf(s_agg[f],   W_n[(FD + f) * FD + m], acc);
#pragma unroll 8
        for (int f = 0; f < FD; f++)  acc = fmaf(s_attn[f],  W_n[(2 * FD + f) * FD + m], acc);
        out[(size_t)n_i * FD + m] = acc;
    }
    if (t >= 64 && t < 67) {
        int c = t - 64;
        float xs = 0.f;
#pragma unroll
        for (int w2 = 0; w2 < 8; w2++) xs += s_xp[w2][c];
        out[(size_t)BN * FD + n_i * 3 + c] = x[n_i * 3 + c] + xs;
    }
}

extern "C" void kernel_launch(void* const* d_in, const int* in_sizes, int n_in,
                              void* d_out, int out_size) {
    const float* h    = (const float*)d_in[0];
    const float* x    = (const float*)d_in[1];
    const float* W_ew = (const float*)d_in[2];
    const float* b_ew = (const float*)d_in[3];
    const float* W_sa = (const float*)d_in[4];
    const float* W_es = (const float*)d_in[5];
    const float* b_es = (const float*)d_in[6];
    const float* W_c1 = (const float*)d_in[7];
    const float* b_c1 = (const float*)d_in[8];
    const float* W_c2 = (const float*)d_in[9];
    const float* b_c2 = (const float*)d_in[10];
    const float* W_n  = (const float*)d_in[11];
    const float* b_n  = (const float*)d_in[12];
    float* out = (float*)d_out;

    sake_pre<<<BN, 64>>>(h, W_ew, W_es, W_sa);
    sake_main<<<BN, 256>>>(h, x, b_ew, W_es, b_es, W_c1, b_c1, W_c2, b_c2, W_n, b_n, out);
}

// round 4
// speedup vs baseline: 2.2936x; 1.3654x over previous
#include <cuda_runtime.h>
#include <cuda_bf16.h>
#include <cstdint>
#include <cstddef>

#define NN 512
#define BN 2048
#define FD 64
#define EPSV 1e-14f

typedef unsigned long long ull;
typedef unsigned int u32;

// ---------------- scratch ----------------
__device__ float g_pj_ew[BN * FD];
__device__ float g_pi_ew[BN * FD];
__device__ float g_pjesT[BN * FD];   // [b][h][j]
__device__ float g_pi_es[BN * FD];
__device__ float g_pj_sa[BN];
__device__ float g_pi_sa[BN];

// ---------------- helpers ----------------
__device__ __forceinline__ float tanh_hw(float v) {
    float r; asm("tanh.approx.f32 %0, %1;" : "=f"(r) : "f"(v)); return r;
}
__device__ __forceinline__ float silu_hw(float v) {
    float m = 0.5f * v;
    return fmaf(m, tanh_hw(m), m);
}
__device__ __forceinline__ u32 tf32r(float f) {
    u32 r; asm("cvt.rna.tf32.f32 %0, %1;" : "=r"(r) : "f"(f)); return r;
}
__device__ __forceinline__ ull pack2(float lo, float hi) {
    ull r; asm("mov.b64 %0, {%1, %2};" : "=l"(r) : "f"(lo), "f"(hi)); return r;
}
__device__ __forceinline__ void unpack2(ull v, float& lo, float& hi) {
    asm("mov.b64 {%0, %1}, %2;" : "=f"(lo), "=f"(hi) : "l"(v));
}
__device__ __forceinline__ ull add2(ull a, ull b) {
    ull r; asm("add.rn.f32x2 %0, %1, %2;" : "=l"(r) : "l"(a), "l"(b)); return r;
}

// classic tensor-core MMA (sm_80+ PTX, works on plain sm_103 target)
__device__ __forceinline__ void mma_tf32_16x8x8(float d[4], const u32 a[4], const u32 b[2]) {
    asm volatile("mma.sync.aligned.m16n8k8.row.col.f32.tf32.tf32.f32 "
        "{%0,%1,%2,%3}, {%4,%5,%6,%7}, {%8,%9}, {%0,%1,%2,%3};"
        : "+f"(d[0]), "+f"(d[1]), "+f"(d[2]), "+f"(d[3])
        : "r"(a[0]), "r"(a[1]), "r"(a[2]), "r"(a[3]), "r"(b[0]), "r"(b[1]));
}

#define APAD 65   // row pitch (floats) for he tiles -> conflict-free STS
#define BPAD 65   // row pitch for W_c1 tile

struct __align__(16) SMEM {
    float A[8][32 * APAD];   // per-warp he tile (tf32 bits), [j(32)][h(64)] pad 65
    float B[FD * BPAD];      // W_c1 (tf32 bits), [h][m] pad 65
    float xmx[NN * 3];
    float v3[NN * 3];
    float filt[NN];
    float sw[NN];
    float piew[FD], pies[FD], wes0[FD], bc1[FD], wc2[FD];
    float attp[4][FD][3];
    float aggp[8][FD];
    float agg[FD], attn[FD];
    float xp[8][3];
    float red[8];
    float scal;
};

// ---------------- kernel A: node-level projections ----------------
__global__ void sake_pre(const float* __restrict__ h,
                         const float* __restrict__ W_ew,
                         const float* __restrict__ W_es,
                         const float* __restrict__ W_sa) {
    int n = blockIdx.x;
    int k = threadIdx.x;
    __shared__ float sh[FD];
    __shared__ float sp1[FD], sp2[FD];
    sh[k] = h[n * FD + k];
    __syncthreads();
    float a_jew = 0.f, a_iew = 0.f, a_jes = 0.f, a_ies = 0.f;
#pragma unroll 8
    for (int f = 0; f < FD; f++) {
        float hf = sh[f];
        a_jew = fmaf(hf, W_ew[f * FD + k], a_jew);
        a_iew = fmaf(hf, W_ew[(FD + f) * FD + k], a_iew);
        a_jes = fmaf(hf, W_es[(1 + f) * FD + k], a_jes);
        a_ies = fmaf(hf, W_es[(1 + FD + f) * FD + k], a_ies);
    }
    g_pj_ew[n * FD + k] = a_jew;
    g_pi_ew[n * FD + k] = a_iew;
    int b = n >> 9, j = n & 511;
    g_pjesT[(b * FD + k) * NN + j] = a_jes;
    g_pi_es[n * FD + k] = a_ies;
    sp1[k] = sh[k] * W_sa[k];
    sp2[k] = sh[k] * W_sa[FD + k];
    __syncthreads();
    if (k == 0) { float s = 0.f; for (int f = 0; f < FD; f++) s += sp1[f]; g_pj_sa[n] = s; }
    if (k == 1) { float s = 0.f; for (int f = 0; f < FD; f++) s += sp2[f]; g_pi_sa[n] = s; }
}

// ---------------- kernel B: fused pairwise main (mma.sync matvec) ----------------
__global__ __launch_bounds__(256, 2) void sake_main(
    const float* __restrict__ h, const float* __restrict__ x,
    const float* __restrict__ b_ew, const float* __restrict__ W_es,
    const float* __restrict__ b_es, const float* __restrict__ W_c1,
    const float* __restrict__ b_c1, const float* __restrict__ W_c2,
    const float* __restrict__ b_c2, const float* __restrict__ W_n,
    const float* __restrict__ b_n, float* __restrict__ out)
{
    extern __shared__ __align__(16) char dsm_raw[];
    SMEM* S = (SMEM*)dsm_raw;

    const int n_i = blockIdx.x;
    const int b = n_i >> 9;
    const int t = threadIdx.x;
    const int warp = t >> 5, lane = t & 31;

    // ---- stage B tile: B[h][m] = tf32(W_c1[h][m]) ----
    for (int idx = t; idx < FD * FD; idx += 256) {
        int hh = idx >> 6, m = idx & 63;
        S->B[hh * BPAD + m] = __uint_as_float(tf32r(W_c1[idx]));
    }
    if (t < FD) {
        S->piew[t] = g_pi_ew[n_i * FD + t] + b_ew[t];
        S->pies[t] = g_pi_es[n_i * FD + t] + b_es[t];
        S->wes0[t] = W_es[t];
        S->bc1[t]  = b_c1[t];
        S->wc2[t]  = W_c2[t];
    }

    const float xi0 = x[n_i * 3 + 0], xi1 = x[n_i * 3 + 1], xi2 = x[n_i * 3 + 2];
    const float pi_sa_v = g_pi_sa[n_i];
    const float bc2v = b_c2[0];

    // ---- pass 1: per-j geometry + softmax numerators ----
    float esum = 0.f;
    for (int j = t; j < NN; j += 256) {
        float dx = x[(b * NN + j) * 3 + 0] - xi0;
        float dy = x[(b * NN + j) * 3 + 1] - xi1;
        float dz = x[(b * NN + j) * 3 + 2] - xi2;
        float d2 = dx * dx + dy * dy + dz * dz;
        float nrm = sqrtf(d2 + EPSV);
        S->xmx[j * 3 + 0] = dx; S->xmx[j * 3 + 1] = dy; S->xmx[j * 3 + 2] = dz;
        float inv2 = 1.0f / (nrm * nrm + EPSV);
        S->v3[j * 3 + 0] = dx * inv2; S->v3[j * 3 + 1] = dy * inv2; S->v3[j * 3 + 2] = dz * inv2;
        S->filt[j] = 1.0f / (nrm + 0.1f);
        float en = __expf(nrm);
        esum += en;
        float sem = g_pj_sa[b * NN + j] + pi_sa_v;
        sem = (sem > 0.f) ? sem : 0.01f * sem;
        S->sw[j] = sem * en;
    }
#pragma unroll
    for (int o = 16; o; o >>= 1) esum += __shfl_xor_sync(0xffffffffu, esum, o);
    if (lane == 0) S->red[warp] = esum;
    __syncthreads();
    if (t == 0) {
        float s = 0.f;
#pragma unroll
        for (int w = 0; w < 8; w++) s += S->red[w];
        S->scal = 1.0f / s;
    }
    __syncthreads();

    // ---- pass 2: att_sum einsum ----
    {
        int k = t & 63, jb = t >> 6;
        float base = S->piew[k];
        const float* pjew = g_pj_ew + (size_t)(b * NN) * FD + k;
        float a0 = 0.f, a1 = 0.f, a2 = 0.f;
        int j0 = jb * 128;
#pragma unroll 4
        for (int jj = 0; jj < 128; jj++) {
            int j = j0 + jj;
            float e = tanh_hw(pjew[(size_t)j * FD] + base);
            a0 = fmaf(e, S->v3[j * 3 + 0], a0);
            a1 = fmaf(e, S->v3[j * 3 + 1], a1);
            a2 = fmaf(e, S->v3[j * 3 + 2], a2);
        }
        S->attp[jb][k][0] = a0; S->attp[jb][k][1] = a1; S->attp[jb][k][2] = a2;
    }
    __syncthreads();

    const float inv_sum = S->scal;
    const float* pjes = g_pjesT + (size_t)(b * FD) * NN;
    float* Aw = S->A[warp];

    ull aggacc = 0ull;
    float xacc0 = 0.f, xacc1 = 0.f, xacc2 = 0.f;

    // ================= 2 rounds of 32 j per warp =================
    for (int rnd = 0; rnd < 2; rnd++) {
        const int j = warp * 64 + rnd * 32 + lane;

        // ---- he generation (exact fp32 for agg; tf32 bits into A tile) ----
        {
            const float filt = S->filt[j];
            const float w = S->sw[j] * inv_sum;
            ull hep[32];
#pragma unroll
            for (int qq = 0; qq < 16; qq++) {
                const int h0 = qq * 4;
                float p0 = pjes[(size_t)(h0 + 0) * NN + j] + fmaf(filt, S->wes0[h0 + 0], S->pies[h0 + 0]);
                float p1 = pjes[(size_t)(h0 + 1) * NN + j] + fmaf(filt, S->wes0[h0 + 1], S->pies[h0 + 1]);
                float p2 = pjes[(size_t)(h0 + 2) * NN + j] + fmaf(filt, S->wes0[h0 + 2], S->pies[h0 + 2]);
                float p3 = pjes[(size_t)(h0 + 3) * NN + j] + fmaf(filt, S->wes0[h0 + 3], S->pies[h0 + 3]);
                float e0 = silu_hw(p0), e1 = silu_hw(p1), e2 = silu_hw(p2), e3 = silu_hw(p3);
                Aw[lane * APAD + h0 + 0] = __uint_as_float(tf32r(e0));
                Aw[lane * APAD + h0 + 1] = __uint_as_float(tf32r(e1));
                Aw[lane * APAD + h0 + 2] = __uint_as_float(tf32r(e2));
                Aw[lane * APAD + h0 + 3] = __uint_as_float(tf32r(e3));
                hep[2 * qq]     = pack2(w * e0, w * e1);
                hep[2 * qq + 1] = pack2(w * e2, w * e3);
            }
            // weighted tree-reduce across lanes (64 h values -> 2 per lane)
#pragma unroll
            for (int ph = 0; ph < 5; ph++) {
                const int L = 32 >> ph;
                const bool hi = (lane >> ph) & 1;
#pragma unroll
                for (int k2 = 0; k2 < 16; k2++) {
                    if (k2 < (L >> 1)) {
                        ull keep = hi ? hep[k2 + (L >> 1)] : hep[k2];
                        ull send = hi ? hep[k2] : hep[k2 + (L >> 1)];
                        ull rec = __shfl_xor_sync(0xffffffffu, send, 1 << ph);
                        hep[k2] = add2(keep, rec);
                    }
                }
            }
            aggacc = add2(aggacc, hep[0]);
        }
        __syncwarp();

        // ---- MMA: D[32j x 64m] = he @ W_c1, two 16-row jtiles ----
        const int r4 = lane >> 2, c4 = lane & 3;
#pragma unroll
        for (int jt = 0; jt < 2; jt++) {
            float D[8][4];
#pragma unroll
            for (int nt = 0; nt < 8; nt++) { D[nt][0] = D[nt][1] = D[nt][2] = D[nt][3] = 0.f; }
            const int jr = jt * 16 + r4;
#pragma unroll
            for (int kt = 0; kt < 8; kt++) {
                const int kb = kt * 8;
                u32 a[4];
                a[0] = __float_as_uint(Aw[jr * APAD + kb + c4]);
                a[1] = __float_as_uint(Aw[(jr + 8) * APAD + kb + c4]);
                a[2] = __float_as_uint(Aw[jr * APAD + kb + 4 + c4]);
                a[3] = __float_as_uint(Aw[(jr + 8) * APAD + kb + 4 + c4]);
#pragma unroll
                for (int nt = 0; nt < 8; nt++) {
                    const int nb = nt * 8;
                    u32 bb[2];
                    bb[0] = __float_as_uint(S->B[(kb + c4) * BPAD + nb + r4]);
                    bb[1] = __float_as_uint(S->B[(kb + 4 + c4) * BPAD + nb + r4]);
                    mma_tf32_16x8x8(D[nt], a, bb);
                }
            }
            // ---- epilogue: silu -> dot wc2 -> coord -> x accumulation ----
            float cs0 = 0.f, cs1 = 0.f;
#pragma unroll
            for (int nt = 0; nt < 8; nt++) {
                const int c0 = nt * 8 + 2 * c4, c1 = c0 + 1;
                const float bcA = S->bc1[c0], bcB = S->bc1[c1];
                const float wcA = S->wc2[c0], wcB = S->wc2[c1];
                cs0 = fmaf(silu_hw(D[nt][0] + bcA), wcA, cs0);
                cs0 = fmaf(silu_hw(D[nt][1] + bcB), wcB, cs0);
                cs1 = fmaf(silu_hw(D[nt][2] + bcA), wcA, cs1);
                cs1 = fmaf(silu_hw(D[nt][3] + bcB), wcB, cs1);
            }
            cs0 += __shfl_xor_sync(0xffffffffu, cs0, 1);
            cs0 += __shfl_xor_sync(0xffffffffu, cs0, 2);
            cs1 += __shfl_xor_sync(0xffffffffu, cs1, 1);
            cs1 += __shfl_xor_sync(0xffffffffu, cs1, 2);
            if (c4 == 0) {
                const int j0 = warp * 64 + rnd * 32 + jt * 16 + r4;
                const int j1 = j0 + 8;
                float coord0 = cs0 + bc2v, coord1 = cs1 + bc2v;
                xacc0 = fmaf(S->xmx[j0 * 3 + 0], coord0, xacc0);
                xacc1 = fmaf(S->xmx[j0 * 3 + 1], coord0, xacc1);
                xacc2 = fmaf(S->xmx[j0 * 3 + 2], coord0, xacc2);
                xacc0 = fmaf(S->xmx[j1 * 3 + 0], coord1, xacc0);
                xacc1 = fmaf(S->xmx[j1 * 3 + 1], coord1, xacc1);
                xacc2 = fmaf(S->xmx[j1 * 3 + 2], coord1, xacc2);
            }
        }
        __syncwarp();   // A tile reused next round
    }

    // agg partials (bit-reversed lane -> k mapping of the tree)
    {
        int kk = ((lane & 1) << 4) | (((lane >> 1) & 1) << 3) | (((lane >> 2) & 1) << 2)
               | (((lane >> 3) & 1) << 1) | ((lane >> 4) & 1);
        float glo, ghi;
        unpack2(aggacc, glo, ghi);
        S->aggp[warp][2 * kk]     = glo;
        S->aggp[warp][2 * kk + 1] = ghi;
    }
#pragma unroll
    for (int o = 16; o; o >>= 1) {
        xacc0 += __shfl_xor_sync(0xffffffffu, xacc0, o);
        xacc1 += __shfl_xor_sync(0xffffffffu, xacc1, o);
        xacc2 += __shfl_xor_sync(0xffffffffu, xacc2, o);
    }
    if (lane == 0) { S->xp[warp][0] = xacc0; S->xp[warp][1] = xacc1; S->xp[warp][2] = xacc2; }
    __syncthreads();

    // ---- finalize att_norm and h_e_agg ----
    if (t < FD) {
        float a0 = S->attp[0][t][0] + S->attp[1][t][0] + S->attp[2][t][0] + S->attp[3][t][0];
        float a1 = S->attp[0][t][1] + S->attp[1][t][1] + S->attp[2][t][1] + S->attp[3][t][1];
        float a2 = S->attp[0][t][2] + S->attp[1][t][2] + S->attp[2][t][2] + S->attp[3][t][2];
        S->attn[t] = sqrtf(a0 * a0 + a1 * a1 + a2 * a2 + EPSV);
        float ag = 0.f;
#pragma unroll
        for (int w2 = 0; w2 < 8; w2++) ag += S->aggp[w2][t];
        S->agg[t] = ag;
    }
    __syncthreads();

    // ---- h_new = concat(h, agg, attn) @ W_n + b_n ----
    if (t < FD) {
        int m = t;
        float acc = b_n[m];
        const float* hi2 = h + (size_t)n_i * FD;
#pragma unroll 8
        for (int f = 0; f < FD; f++)  acc = fmaf(hi2[f],      W_n[f * FD + m], acc);
#pragma unroll 8
        for (int f = 0; f < FD; f++)  acc = fmaf(S->agg[f],   W_n[(FD + f) * FD + m], acc);
#pragma unroll 8
        for (int f = 0; f < FD; f++)  acc = fmaf(S->attn[f],  W_n[(2 * FD + f) * FD + m], acc);
        out[(size_t)n_i * FD + m] = acc;
    }
    if (t >= 64 && t < 67) {
        int c = t - 64;
        float xs = 0.f;
#pragma unroll
        for (int w2 = 0; w2 < 8; w2++) xs += S->xp[w2][c];
        out[(size_t)BN * FD + n_i * 3 + c] = x[n_i * 3 + c] + xs;
    }
}

extern "C" void kernel_launch(void* const* d_in, const int* in_sizes, int n_in,
                              void* d_out, int out_size) {
    const float* h    = (const float*)d_in[0];
    const float* x    = (const float*)d_in[1];
    const float* W_ew = (const float*)d_in[2];
    const float* b_ew = (const float*)d_in[3];
    const float* W_sa = (const float*)d_in[4];
    const float* W_es = (const float*)d_in[5];
    const float* b_es = (const float*)d_in[6];
    const float* W_c1 = (const float*)d_in[7];
    const float* b_c1 = (const float*)d_in[8];
    const float* W_c2 = (const float*)d_in[9];
    const float* b_c2 = (const float*)d_in[10];
    const float* W_n  = (const float*)d_in[11];
    const float* b_n  = (const float*)d_in[12];
    float* out = (float*)d_out;

    const int smem_bytes = (int)sizeof(SMEM);
    cudaFuncSetAttribute(sake_main, cudaFuncAttributeMaxDynamicSharedMemorySize, smem_bytes);

    sake_pre<<<BN, 64>>>(h, W_ew, W_es, W_sa);
    sake_main<<<BN, 256, smem_bytes>>>(h, x, b_ew, W_es, b_es, W_c1, b_c1, W_c2, b_c2, W_n, b_n, out);
}

// round 6
// speedup vs baseline: 3.4847x; 1.5193x over previous
#include <cuda_runtime.h>
#include <cuda_bf16.h>
#include <cstdint>
#include <cstddef>

#define NN 512
#define BN 2048
#define FD 64
#define EPSV 1e-14f

typedef unsigned long long ull;
typedef unsigned int u32;

// ---------------- scratch ----------------
__device__ float g_pj_ew[BN * FD];
__device__ float g_pi_ew[BN * FD];
__device__ float g_pjesT[BN * FD];   // [b][h][j]
__device__ float g_pi_es[BN * FD];
__device__ float g_pj_sa[BN];
__device__ float g_pi_sa[BN];

// ---------------- helpers ----------------
__device__ __forceinline__ float tanh_hw(float v) {
    float r; asm("tanh.approx.f32 %0, %1;" : "=f"(r) : "f"(v)); return r;
}
__device__ __forceinline__ float silu_hw(float v) {
    float m = 0.5f * v;
    return fmaf(m, tanh_hw(m), m);
}
__device__ __forceinline__ u32 tf32r(float f) {
    u32 r; asm("cvt.rna.tf32.f32 %0, %1;" : "=r"(r) : "f"(f)); return r;
}

// classic tensor-core MMA (sm_80+ PTX, works on plain sm_103 target)
__device__ __forceinline__ void mma_tf32_16x8x8(float d[4], const u32 a[4], const u32 b[2]) {
    asm volatile("mma.sync.aligned.m16n8k8.row.col.f32.tf32.tf32.f32 "
        "{%0,%1,%2,%3}, {%4,%5,%6,%7}, {%8,%9}, {%0,%1,%2,%3};"
        : "+f"(d[0]), "+f"(d[1]), "+f"(d[2]), "+f"(d[3])
        : "r"(a[0]), "r"(a[1]), "r"(a[2]), "r"(a[3]), "r"(b[0]), "r"(b[1]));
}

#define STS128S(ad, r0, r1, r2, r3) \
    asm volatile("st.shared.v4.b32 [%0], {%1,%2,%3,%4};" :: "r"(ad), "r"(r0), "r"(r1), "r"(r2), "r"(r3) : "memory")

#define APAD 68   // row pitch (floats): 272B rows -> 16B-aligned v4 stores; A-frag banks (4*r4+c4) all distinct
#define BPAD 72   // row pitch: 72 % 32 == 8 -> B-frag banks (8*c4+r4) all distinct (conflict-free)

struct __align__(16) SMEM {
    float A[8][16 * APAD];   // per-warp he subtile (tf32 bits), [j(16)][h(64)]
    float B[FD * BPAD];      // W_c1 (tf32 bits), [h][m]
    float xmx[NN * 3];
    float inv2[NN];
    float filt[NN];
    float sw[NN];
    float piew[FD], pies[FD], wes0[FD], bc1[FD], wc2[FD];
    float attp[4][FD][3];
    float aggp[8][FD];
    float agg[FD], attn[FD];
    float xp[8][3];
    float red[8];
    float scal;
};

// ---------------- kernel A: node-level projections ----------------
__global__ void sake_pre(const float* __restrict__ h,
                         const float* __restrict__ W_ew,
                         const float* __restrict__ W_es,
                         const float* __restrict__ W_sa) {
    int n = blockIdx.x;
    int k = threadIdx.x;
    __shared__ float sh[FD];
    __shared__ float sp1[FD], sp2[FD];
    sh[k] = h[n * FD + k];
    __syncthreads();
    float a_jew = 0.f, a_iew = 0.f, a_jes = 0.f, a_ies = 0.f;
#pragma unroll 8
    for (int f = 0; f < FD; f++) {
        float hf = sh[f];
        a_jew = fmaf(hf, W_ew[f * FD + k], a_jew);
        a_iew = fmaf(hf, W_ew[(FD + f) * FD + k], a_iew);
        a_jes = fmaf(hf, W_es[(1 + f) * FD + k], a_jes);
        a_ies = fmaf(hf, W_es[(1 + FD + f) * FD + k], a_ies);
    }
    g_pj_ew[n * FD + k] = a_jew;
    g_pi_ew[n * FD + k] = a_iew;
    int b = n >> 9, j = n & 511;
    g_pjesT[(b * FD + k) * NN + j] = a_jes;
    g_pi_es[n * FD + k] = a_ies;
    sp1[k] = sh[k] * W_sa[k];
    sp2[k] = sh[k] * W_sa[FD + k];
    __syncthreads();
    if (k == 0) { float s = 0.f; for (int f = 0; f < FD; f++) s += sp1[f]; g_pj_sa[n] = s; }
    if (k == 1) { float s = 0.f; for (int f = 0; f < FD; f++) s += sp2[f]; g_pi_sa[n] = s; }
}

// ---------------- kernel B: fused pairwise main ----------------
__global__ __launch_bounds__(256, 3) void sake_main(
    const float* __restrict__ h, const float* __restrict__ x,
    const float* __restrict__ b_ew, const float* __restrict__ W_es,
    const float* __restrict__ b_es, const float* __restrict__ W_c1,
    const float* __restrict__ b_c1, const float* __restrict__ W_c2,
    const float* __restrict__ b_c2, const float* __restrict__ W_n,
    const float* __restrict__ b_n, float* __restrict__ out)
{
    extern __shared__ __align__(16) char dsm_raw[];
    SMEM* S = (SMEM*)dsm_raw;

    const int n_i = blockIdx.x;
    const int b = n_i >> 9;
    const int t = threadIdx.x;
    const int warp = t >> 5, lane = t & 31;

    // ---- stage B tile: B[h][m] = tf32(W_c1[h][m]) ----
    for (int idx = t; idx < FD * FD; idx += 256) {
        int hh = idx >> 6, m = idx & 63;
        S->B[hh * BPAD + m] = __uint_as_float(tf32r(W_c1[idx]));
    }
    if (t < FD) {
        S->piew[t] = g_pi_ew[n_i * FD + t] + b_ew[t];
        S->pies[t] = g_pi_es[n_i * FD + t] + b_es[t];
        S->wes0[t] = W_es[t];
        S->bc1[t]  = b_c1[t];
        S->wc2[t]  = W_c2[t];
    }

    const float xi0 = x[n_i * 3 + 0], xi1 = x[n_i * 3 + 1], xi2 = x[n_i * 3 + 2];
    const float pi_sa_v = g_pi_sa[n_i];
    const float bc2v = b_c2[0];

    // ---- pass 1: per-j geometry + softmax numerators ----
    float esum = 0.f;
    for (int j = t; j < NN; j += 256) {
        float dx = x[(b * NN + j) * 3 + 0] - xi0;
        float dy = x[(b * NN + j) * 3 + 1] - xi1;
        float dz = x[(b * NN + j) * 3 + 2] - xi2;
        float d2 = dx * dx + dy * dy + dz * dz;
        float nrm = sqrtf(d2 + EPSV);
        S->xmx[j * 3 + 0] = dx; S->xmx[j * 3 + 1] = dy; S->xmx[j * 3 + 2] = dz;
        S->inv2[j] = 1.0f / (nrm * nrm + EPSV);
        S->filt[j] = 1.0f / (nrm + 0.1f);
        float en = __expf(nrm);
        esum += en;
        float sem = g_pj_sa[b * NN + j] + pi_sa_v;
        sem = (sem > 0.f) ? sem : 0.01f * sem;
        S->sw[j] = sem * en;
    }
#pragma unroll
    for (int o = 16; o; o >>= 1) esum += __shfl_xor_sync(0xffffffffu, esum, o);
    if (lane == 0) S->red[warp] = esum;
    __syncthreads();
    if (t == 0) {
        float s = 0.f;
#pragma unroll
        for (int w = 0; w < 8; w++) s += S->red[w];
        S->scal = 1.0f / s;
    }
    __syncthreads();

    // ---- pass 2: att_sum einsum ----
    {
        int k = t & 63, jb = t >> 6;
        float base = S->piew[k];
        const float* pjew = g_pj_ew + (size_t)(b * NN) * FD + k;
        float a0 = 0.f, a1 = 0.f, a2 = 0.f;
        int j0 = jb * 128;
#pragma unroll 4
        for (int jj = 0; jj < 128; jj++) {
            int j = j0 + jj;
            float e = tanh_hw(pjew[(size_t)j * FD] + base);
            float ei = e * S->inv2[j];
            a0 = fmaf(ei, S->xmx[j * 3 + 0], a0);
            a1 = fmaf(ei, S->xmx[j * 3 + 1], a1);
            a2 = fmaf(ei, S->xmx[j * 3 + 2], a2);
        }
        S->attp[jb][k][0] = a0; S->attp[jb][k][1] = a1; S->attp[jb][k][2] = a2;
    }
    __syncthreads();

    const float inv_sum = S->scal;
    const float* pjes = g_pjesT + (size_t)(b * FD) * NN;
    float* Aw = S->A[warp];
    const u32 Aw_ad = (u32)__cvta_generic_to_shared(Aw);

    float xacc0 = 0.f, xacc1 = 0.f, xacc2 = 0.f;
    float agg0 = 0.f, agg1 = 0.f;     // lane owns h=lane, h=lane+32
    const int r4 = lane >> 2, c4 = lane & 3;
    const int row = lane >> 1, sh2 = (lane & 1) << 5;   // he-gen mapping

    // ================= 4 subtiles of 16 j per warp =================
    for (int sub = 0; sub < 4; sub++) {
        const int jb = warp * 64 + sub * 16;

        // ---- he generation: 2 lanes per row, 32 h each ----
        {
            const int j = jb + row;
            const float filt = S->filt[j];
#pragma unroll
            for (int q = 0; q < 8; q++) {
                const int h0 = sh2 + q * 4;
                float p0 = pjes[(size_t)(h0 + 0) * NN + j] + fmaf(filt, S->wes0[h0 + 0], S->pies[h0 + 0]);
                float p1 = pjes[(size_t)(h0 + 1) * NN + j] + fmaf(filt, S->wes0[h0 + 1], S->pies[h0 + 1]);
                float p2 = pjes[(size_t)(h0 + 2) * NN + j] + fmaf(filt, S->wes0[h0 + 2], S->pies[h0 + 2]);
                float p3 = pjes[(size_t)(h0 + 3) * NN + j] + fmaf(filt, S->wes0[h0 + 3], S->pies[h0 + 3]);
                STS128S(Aw_ad + (u32)(row * APAD + h0) * 4,
                        tf32r(silu_hw(p0)), tf32r(silu_hw(p1)),
                        tf32r(silu_hw(p2)), tf32r(silu_hw(p3)));
            }
        }
        __syncwarp();

        // ---- MMA: D[16j x 64m] = he @ W_c1 ----
        float D[8][4];
#pragma unroll
        for (int nt = 0; nt < 8; nt++) { D[nt][0] = D[nt][1] = D[nt][2] = D[nt][3] = 0.f; }
#pragma unroll
        for (int kt = 0; kt < 8; kt++) {
            const int kb = kt * 8;
            u32 a[4];
            a[0] = __float_as_uint(Aw[r4 * APAD + kb + c4]);
            a[1] = __float_as_uint(Aw[(r4 + 8) * APAD + kb + c4]);
            a[2] = __float_as_uint(Aw[r4 * APAD + kb + 4 + c4]);
            a[3] = __float_as_uint(Aw[(r4 + 8) * APAD + kb + 4 + c4]);
#pragma unroll
            for (int nt = 0; nt < 8; nt++) {
                const int nb = nt * 8;
                u32 bb[2];
                bb[0] = __float_as_uint(S->B[(kb + c4) * BPAD + nb + r4]);
                bb[1] = __float_as_uint(S->B[(kb + 4 + c4) * BPAD + nb + r4]);
                mma_tf32_16x8x8(D[nt], a, bb);
            }
        }

        // ---- epilogue: silu -> dot wc2 -> coord -> x accumulation ----
        {
            float cs0 = 0.f, cs1 = 0.f;
#pragma unroll
            for (int nt = 0; nt < 8; nt++) {
                const int c0 = nt * 8 + 2 * c4, c1 = c0 + 1;
                const float bcA = S->bc1[c0], bcB = S->bc1[c1];
                const float wcA = S->wc2[c0], wcB = S->wc2[c1];
                cs0 = fmaf(silu_hw(D[nt][0] + bcA), wcA, cs0);
                cs0 = fmaf(silu_hw(D[nt][1] + bcB), wcB, cs0);
                cs1 = fmaf(silu_hw(D[nt][2] + bcA), wcA, cs1);
                cs1 = fmaf(silu_hw(D[nt][3] + bcB), wcB, cs1);
            }
            cs0 += __shfl_xor_sync(0xffffffffu, cs0, 1);
            cs0 += __shfl_xor_sync(0xffffffffu, cs0, 2);
            cs1 += __shfl_xor_sync(0xffffffffu, cs1, 1);
            cs1 += __shfl_xor_sync(0xffffffffu, cs1, 2);
            if (c4 == 0) {
                const int j0 = jb + r4, j1 = j0 + 8;
                float coord0 = cs0 + bc2v, coord1 = cs1 + bc2v;
                xacc0 = fmaf(S->xmx[j0 * 3 + 0], coord0, xacc0);
                xacc1 = fmaf(S->xmx[j0 * 3 + 1], coord0, xacc1);
                xacc2 = fmaf(S->xmx[j0 * 3 + 2], coord0, xacc2);
                xacc0 = fmaf(S->xmx[j1 * 3 + 0], coord1, xacc0);
                xacc1 = fmaf(S->xmx[j1 * 3 + 1], coord1, xacc1);
                xacc2 = fmaf(S->xmx[j1 * 3 + 2], coord1, xacc2);
            }
        }

        // ---- h_e_agg from staged A columns (banks (4*jj+lane)%32: conflict-free) ----
#pragma unroll 4
        for (int jj = 0; jj < 16; jj++) {
            float w = S->sw[jb + jj] * inv_sum;
            agg0 = fmaf(w, Aw[jj * APAD + lane],      agg0);
            agg1 = fmaf(w, Aw[jj * APAD + lane + 32], agg1);
        }
        __syncwarp();   // A reused next subtile
    }

    S->aggp[warp][lane]      = agg0;
    S->aggp[warp][lane + 32] = agg1;
#pragma unroll
    for (int o = 16; o; o >>= 1) {
        xacc0 += __shfl_xor_sync(0xffffffffu, xacc0, o);
        xacc1 += __shfl_xor_sync(0xffffffffu, xacc1, o);
        xacc2 += __shfl_xor_sync(0xffffffffu, xacc2, o);
    }
    if (lane == 0) { S->xp[warp][0] = xacc0; S->xp[warp][1] = xacc1; S->xp[warp][2] = xacc2; }
    __syncthreads();

    // ---- finalize att_norm and h_e_agg ----
    if (t < FD) {
        float a0 = S->attp[0][t][0] + S->attp[1][t][0] + S->attp[2][t][0] + S->attp[3][t][0];
        float a1 = S->attp[0][t][1] + S->attp[1][t][1] + S->attp[2][t][1] + S->attp[3][t][1];
        float a2 = S->attp[0][t][2] + S->attp[1][t][2] + S->attp[2][t][2] + S->attp[3][t][2];
        S->attn[t] = sqrtf(a0 * a0 + a1 * a1 + a2 * a2 + EPSV);
        float ag = 0.f;
#pragma unroll
        for (int w2 = 0; w2 < 8; w2++) ag += S->aggp[w2][t];
        S->agg[t] = ag;
    }
    __syncthreads();

    // ---- h_new = concat(h, agg, attn) @ W_n + b_n ----
    if (t < FD) {
        int m = t;
        float acc = b_n[m];
        const float* hi2 = h + (size_t)n_i * FD;
#pragma unroll 8
        for (int f = 0; f < FD; f++)  acc = fmaf(hi2[f],      W_n[f * FD + m], acc);
#pragma unroll 8
        for (int f = 0; f < FD; f++)  acc = fmaf(S->agg[f],   W_n[(FD + f) * FD + m], acc);
#pragma unroll 8
        for (int f = 0; f < FD; f++)  acc = fmaf(S->attn[f],  W_n[(2 * FD + f) * FD + m], acc);
        out[(size_t)n_i * FD + m] = acc;
    }
    if (t >= 64 && t < 67) {
        int c = t - 64;
        float xs = 0.f;
#pragma unroll
        for (int w2 = 0; w2 < 8; w2++) xs += S->xp[w2][c];
        out[(size_t)BN * FD + n_i * 3 + c] = x[n_i * 3 + c] + xs;
    }
}

extern "C" void kernel_launch(void* const* d_in, const int* in_sizes, int n_in,
                              void* d_out, int out_size) {
    const float* h    = (const float*)d_in[0];
    const float* x    = (const float*)d_in[1];
    const float* W_ew = (const float*)d_in[2];
    const float* b_ew = (const float*)d_in[3];
    const float* W_sa = (const float*)d_in[4];
    const float* W_es = (const float*)d_in[5];
    const float* b_es = (const float*)d_in[6];
    const float* W_c1 = (const float*)d_in[7];
    const float* b_c1 = (const float*)d_in[8];
    const float* W_c2 = (const float*)d_in[9];
    const float* b_c2 = (const float*)d_in[10];
    const float* W_n  = (const float*)d_in[11];
    const float* b_n  = (const float*)d_in[12];
    float* out = (float*)d_out;

    const int smem_bytes = (int)sizeof(SMEM);
    cudaFuncSetAttribute(sake_main, cudaFuncAttributeMaxDynamicSharedMemorySize, smem_bytes);

    sake_pre<<<BN, 64>>>(h, W_ew, W_es, W_sa);
    sake_main<<<BN, 256, smem_bytes>>>(h, x, b_ew, W_es, b_es, W_c1, b_c1, W_c2, b_c2, W_n, b_n, out);
}

// round 7
// speedup vs baseline: 3.4924x; 1.0022x over previous
#include <cuda_runtime.h>
#include <cuda_bf16.h>
#include <cstdint>
#include <cstddef>

#define NN 512
#define BN 2048
#define FD 64
#define EPSV 1e-14f

typedef unsigned long long ull;
typedef unsigned int u32;

// ---------------- scratch ----------------
__device__ float g_pj_ew[BN * FD];
__device__ float g_pi_ew[BN * FD];
__device__ float g_pjesT[BN * FD];   // [b][h][j]
__device__ float g_pi_es[BN * FD];
__device__ float g_pj_sa[BN];
__device__ float g_pi_sa[BN];

// ---------------- helpers ----------------
__device__ __forceinline__ float tanh_hw(float v) {
    float r; asm("tanh.approx.f32 %0, %1;" : "=f"(r) : "f"(v)); return r;
}
__device__ __forceinline__ float silu_hw(float v) {
    float m = 0.5f * v;
    return fmaf(m, tanh_hw(m), m);
}
__device__ __forceinline__ u32 tf32r(float f) {
    u32 r; asm("cvt.rna.tf32.f32 %0, %1;" : "=r"(r) : "f"(f)); return r;
}

// classic tensor-core MMA (sm_80+ PTX, works on plain sm_103 target)
__device__ __forceinline__ void mma_tf32_16x8x8(float d[4], const u32 a[4], u32 b0, u32 b1) {
    asm volatile("mma.sync.aligned.m16n8k8.row.col.f32.tf32.tf32.f32 "
        "{%0,%1,%2,%3}, {%4,%5,%6,%7}, {%8,%9}, {%0,%1,%2,%3};"
        : "+f"(d[0]), "+f"(d[1]), "+f"(d[2]), "+f"(d[3])
        : "r"(a[0]), "r"(a[1]), "r"(a[2]), "r"(a[3]), "r"(b0), "r"(b1));
}

#define STS128S(ad, r0, r1, r2, r3) \
    asm volatile("st.shared.v4.b32 [%0], {%1,%2,%3,%4};" :: "r"(ad), "r"(r0), "r"(r1), "r"(r2), "r"(r3) : "memory")

#define APAD 68   // row pitch (floats): 272B rows -> 16B-aligned v4 stores; A-frag banks (4*r4+c4) all distinct

struct __align__(16) SMEM {
    float A[8][16 * APAD];   // per-warp he subtile (tf32 bits), [j(16)][h(64)]
    float Bp[8 * FD * 8];    // W_c1 pair-packed: [kt(8)][m(64)][c4(4)][kk(2)]  (16KB)
    float xmx[NN * 3];
    float inv2[NN];
    float filt[NN];
    float sw[NN];
    float piew[FD], pies[FD], wes0[FD], bc1[FD], wc2[FD];
    float attp[4][FD][3];
    float aggp[8][FD];
    float agg[FD], attn[FD];
    float xp[8][3];
    float red[8];
    float scal;
};

// ---------------- kernel A: node-level projections ----------------
__global__ void sake_pre(const float* __restrict__ h,
                         const float* __restrict__ W_ew,
                         const float* __restrict__ W_es,
                         const float* __restrict__ W_sa) {
    int n = blockIdx.x;
    int k = threadIdx.x;
    __shared__ float sh[FD];
    __shared__ float sp1[FD], sp2[FD];
    sh[k] = h[n * FD + k];
    __syncthreads();
    float a_jew = 0.f, a_iew = 0.f, a_jes = 0.f, a_ies = 0.f;
#pragma unroll 8
    for (int f = 0; f < FD; f++) {
        float hf = sh[f];
        a_jew = fmaf(hf, W_ew[f * FD + k], a_jew);
        a_iew = fmaf(hf, W_ew[(FD + f) * FD + k], a_iew);
        a_jes = fmaf(hf, W_es[(1 + f) * FD + k], a_jes);
        a_ies = fmaf(hf, W_es[(1 + FD + f) * FD + k], a_ies);
    }
    g_pj_ew[n * FD + k] = a_jew;
    g_pi_ew[n * FD + k] = a_iew;
    int b = n >> 9, j = n & 511;
    g_pjesT[(b * FD + k) * NN + j] = a_jes;
    g_pi_es[n * FD + k] = a_ies;
    sp1[k] = sh[k] * W_sa[k];
    sp2[k] = sh[k] * W_sa[FD + k];
    __syncthreads();
    if (k == 0) { float s = 0.f; for (int f = 0; f < FD; f++) s += sp1[f]; g_pj_sa[n] = s; }
    if (k == 1) { float s = 0.f; for (int f = 0; f < FD; f++) s += sp2[f]; g_pi_sa[n] = s; }
}

// ---------------- kernel B: fused pairwise main ----------------
__global__ __launch_bounds__(256, 3) void sake_main(
    const float* __restrict__ h, const float* __restrict__ x,
    const float* __restrict__ b_ew, const float* __restrict__ W_es,
    const float* __restrict__ b_es, const float* __restrict__ W_c1,
    const float* __restrict__ b_c1, const float* __restrict__ W_c2,
    const float* __restrict__ b_c2, const float* __restrict__ W_n,
    const float* __restrict__ b_n, float* __restrict__ out)
{
    extern __shared__ __align__(16) char dsm_raw[];
    SMEM* S = (SMEM*)dsm_raw;

    const int n_i = blockIdx.x;
    const int b = n_i >> 9;
    const int t = threadIdx.x;
    const int warp = t >> 5, lane = t & 31;

    // ---- stage Bp: pair-packed W_c1.  h = kt*8 + c4 + 4*kk ----
    for (int idx = t; idx < FD * FD; idx += 256) {
        int hh = idx >> 6, m = idx & 63;
        int kt = hh >> 3, rem = hh & 7, c4 = rem & 3, kk = rem >> 2;
        S->Bp[(((kt << 6) + m) << 3) + (c4 << 1) + kk] = __uint_as_float(tf32r(W_c1[idx]));
    }
    if (t < FD) {
        S->piew[t] = g_pi_ew[n_i * FD + t] + b_ew[t];
        S->pies[t] = g_pi_es[n_i * FD + t] + b_es[t];
        S->wes0[t] = W_es[t];
        S->bc1[t]  = b_c1[t];
        S->wc2[t]  = W_c2[t];
    }

    const float xi0 = x[n_i * 3 + 0], xi1 = x[n_i * 3 + 1], xi2 = x[n_i * 3 + 2];
    const float pi_sa_v = g_pi_sa[n_i];
    const float bc2v = b_c2[0];

    // ---- pass 1: per-j geometry + softmax numerators ----
    float esum = 0.f;
    for (int j = t; j < NN; j += 256) {
        float dx = x[(b * NN + j) * 3 + 0] - xi0;
        float dy = x[(b * NN + j) * 3 + 1] - xi1;
        float dz = x[(b * NN + j) * 3 + 2] - xi2;
        float d2 = dx * dx + dy * dy + dz * dz;
        float nrm = sqrtf(d2 + EPSV);
        S->xmx[j * 3 + 0] = dx; S->xmx[j * 3 + 1] = dy; S->xmx[j * 3 + 2] = dz;
        S->inv2[j] = 1.0f / (nrm * nrm + EPSV);
        S->filt[j] = 1.0f / (nrm + 0.1f);
        float en = __expf(nrm);
        esum += en;
        float sem = g_pj_sa[b * NN + j] + pi_sa_v;
        sem = (sem > 0.f) ? sem : 0.01f * sem;
        S->sw[j] = sem * en;
    }
#pragma unroll
    for (int o = 16; o; o >>= 1) esum += __shfl_xor_sync(0xffffffffu, esum, o);
    if (lane == 0) S->red[warp] = esum;
    __syncthreads();
    if (t == 0) {
        float s = 0.f;
#pragma unroll
        for (int w = 0; w < 8; w++) s += S->red[w];
        S->scal = 1.0f / s;
    }
    __syncthreads();

    // ---- pass 2: att_sum einsum ----
    {
        int k = t & 63, jb = t >> 6;
        float base = S->piew[k];
        const float* pjew = g_pj_ew + (size_t)(b * NN) * FD + k;
        float a0 = 0.f, a1 = 0.f, a2 = 0.f;
        int j0 = jb * 128;
#pragma unroll 4
        for (int jj = 0; jj < 128; jj++) {
            int j = j0 + jj;
            float e = tanh_hw(pjew[(size_t)j * FD] + base);
            float ei = e * S->inv2[j];
            a0 = fmaf(ei, S->xmx[j * 3 + 0], a0);
            a1 = fmaf(ei, S->xmx[j * 3 + 1], a1);
            a2 = fmaf(ei, S->xmx[j * 3 + 2], a2);
        }
        S->attp[jb][k][0] = a0; S->attp[jb][k][1] = a1; S->attp[jb][k][2] = a2;
    }
    __syncthreads();

    const float* pjes = g_pjesT + (size_t)(b * FD) * NN;
    float* Aw = S->A[warp];
    const u32 Aw_ad = (u32)__cvta_generic_to_shared(Aw);

    float xacc0 = 0.f, xacc1 = 0.f, xacc2 = 0.f;
    float agg0 = 0.f, agg1 = 0.f;     // lane owns h=lane, h=lane+32 (unscaled)
    const int r4 = lane >> 2, c4 = lane & 3;
    const int row = lane >> 1, sh2 = (lane & 1) << 5;   // he-gen mapping

    // ================= 4 subtiles of 16 j per warp =================
    for (int sub = 0; sub < 4; sub++) {
        const int jb = warp * 64 + sub * 16;

        // ---- he generation: 2 lanes per row, 32 h each ----
        {
            const int j = jb + row;
            const float filt = S->filt[j];
#pragma unroll
            for (int q = 0; q < 8; q++) {
                const int h0 = sh2 + q * 4;
                float p0 = pjes[(size_t)(h0 + 0) * NN + j] + fmaf(filt, S->wes0[h0 + 0], S->pies[h0 + 0]);
                float p1 = pjes[(size_t)(h0 + 1) * NN + j] + fmaf(filt, S->wes0[h0 + 1], S->pies[h0 + 1]);
                float p2 = pjes[(size_t)(h0 + 2) * NN + j] + fmaf(filt, S->wes0[h0 + 2], S->pies[h0 + 2]);
                float p3 = pjes[(size_t)(h0 + 3) * NN + j] + fmaf(filt, S->wes0[h0 + 3], S->pies[h0 + 3]);
                STS128S(Aw_ad + (u32)(row * APAD + h0) * 4,
                        tf32r(silu_hw(p0)), tf32r(silu_hw(p1)),
                        tf32r(silu_hw(p2)), tf32r(silu_hw(p3)));
            }
        }
        __syncwarp();

        // ---- MMA: D[16j x 64m] = he @ W_c1 + b_c1 (bias pre-loaded into D) ----
        float D[8][4];
#pragma unroll
        for (int nt = 0; nt < 8; nt++) {
            const float bA = S->bc1[nt * 8 + 2 * c4], bB = S->bc1[nt * 8 + 2 * c4 + 1];
            D[nt][0] = bA; D[nt][1] = bB; D[nt][2] = bA; D[nt][3] = bB;
        }
#pragma unroll
        for (int kt = 0; kt < 8; kt++) {
            const int kb = kt * 8;
            u32 a[4];
            a[0] = __float_as_uint(Aw[r4 * APAD + kb + c4]);
            a[1] = __float_as_uint(Aw[(r4 + 8) * APAD + kb + c4]);
            a[2] = __float_as_uint(Aw[r4 * APAD + kb + 4 + c4]);
            a[3] = __float_as_uint(Aw[(r4 + 8) * APAD + kb + 4 + c4]);
            const float* bprow = S->Bp + ((kt << 6) << 3) + (c4 << 1);
#pragma unroll
            for (int nt = 0; nt < 8; nt++) {
                const int nb = nt * 8;
                ull bv = *(const ull*)(bprow + ((nb + r4) << 3));
                mma_tf32_16x8x8(D[nt], a, (u32)bv, (u32)(bv >> 32));
            }
        }

        // ---- epilogue: silu -> dot wc2 -> coord -> x accumulation ----
        {
            float cs0 = 0.f, cs1 = 0.f;
#pragma unroll
            for (int nt = 0; nt < 8; nt++) {
                const int c0 = nt * 8 + 2 * c4, c1 = c0 + 1;
                const float wcA = S->wc2[c0], wcB = S->wc2[c1];
                cs0 = fmaf(silu_hw(D[nt][0]), wcA, cs0);
                cs0 = fmaf(silu_hw(D[nt][1]), wcB, cs0);
                cs1 = fmaf(silu_hw(D[nt][2]), wcA, cs1);
                cs1 = fmaf(silu_hw(D[nt][3]), wcB, cs1);
            }
            cs0 += __shfl_xor_sync(0xffffffffu, cs0, 1);
            cs0 += __shfl_xor_sync(0xffffffffu, cs0, 2);
            cs1 += __shfl_xor_sync(0xffffffffu, cs1, 1);
            cs1 += __shfl_xor_sync(0xffffffffu, cs1, 2);
            if (c4 == 0) {
                const int j0 = jb + r4, j1 = j0 + 8;
                float coord0 = cs0 + bc2v, coord1 = cs1 + bc2v;
                xacc0 = fmaf(S->xmx[j0 * 3 + 0], coord0, xacc0);
                xacc1 = fmaf(S->xmx[j0 * 3 + 1], coord0, xacc1);
                xacc2 = fmaf(S->xmx[j0 * 3 + 2], coord0, xacc2);
                xacc0 = fmaf(S->xmx[j1 * 3 + 0], coord1, xacc0);
                xacc1 = fmaf(S->xmx[j1 * 3 + 1], coord1, xacc1);
                xacc2 = fmaf(S->xmx[j1 * 3 + 2], coord1, xacc2);
            }
        }

        // ---- h_e_agg from staged A columns (banks (4*jj+lane)%32: conflict-free) ----
#pragma unroll 4
        for (int jj = 0; jj < 16; jj++) {
            float w = S->sw[jb + jj];
            agg0 = fmaf(w, Aw[jj * APAD + lane],      agg0);
            agg1 = fmaf(w, Aw[jj * APAD + lane + 32], agg1);
        }
        __syncwarp();   // A reused next subtile
    }

    S->aggp[warp][lane]      = agg0;
    S->aggp[warp][lane + 32] = agg1;
#pragma unroll
    for (int o = 16; o; o >>= 1) {
        xacc0 += __shfl_xor_sync(0xffffffffu, xacc0, o);
        xacc1 += __shfl_xor_sync(0xffffffffu, xacc1, o);
        xacc2 += __shfl_xor_sync(0xffffffffu, xacc2, o);
    }
    if (lane == 0) { S->xp[warp][0] = xacc0; S->xp[warp][1] = xacc1; S->xp[warp][2] = xacc2; }
    __syncthreads();

    // ---- finalize att_norm and h_e_agg (softmax scale folded in here) ----
    if (t < FD) {
        float a0 = S->attp[0][t][0] + S->attp[1][t][0] + S->attp[2][t][0] + S->attp[3][t][0];
        float a1 = S->attp[0][t][1] + S->attp[1][t][1] + S->attp[2][t][1] + S->attp[3][t][1];
        float a2 = S->attp[0][t][2] + S->attp[1][t][2] + S->attp[2][t][2] + S->attp[3][t][2];
        S->attn[t] = sqrtf(a0 * a0 + a1 * a1 + a2 * a2 + EPSV);
        float ag = 0.f;
#pragma unroll
        for (int w2 = 0; w2 < 8; w2++) ag += S->aggp[w2][t];
        S->agg[t] = ag * S->scal;
    }
    __syncthreads();

    // ---- h_new = concat(h, agg, attn) @ W_n + b_n ----
    if (t < FD) {
        int m = t;
        float acc = b_n[m];
        const float* hi2 = h + (size_t)n_i * FD;
#pragma unroll 8
        for (int f = 0; f < FD; f++)  acc = fmaf(hi2[f],      W_n[f * FD + m], acc);
#pragma unroll 8
        for (int f = 0; f < FD; f++)  acc = fmaf(S->agg[f],   W_n[(FD + f) * FD + m], acc);
#pragma unroll 8
        for (int f = 0; f < FD; f++)  acc = fmaf(S->attn[f],  W_n[(2 * FD + f) * FD + m], acc);
        out[(size_t)n_i * FD + m] = acc;
    }
    if (t >= 64 && t < 67) {
        int c = t - 64;
        float xs = 0.f;
#pragma unroll
        for (int w2 = 0; w2 < 8; w2++) xs += S->xp[w2][c];
        out[(size_t)BN * FD + n_i * 3 + c] = x[n_i * 3 + c] + xs;
    }
}

extern "C" void kernel_launch(void* const* d_in, const int* in_sizes, int n_in,
                              void* d_out, int out_size) {
    const float* h    = (const float*)d_in[0];
    const float* x    = (const float*)d_in[1];
    const float* W_ew = (const float*)d_in[2];
    const float* b_ew = (const float*)d_in[3];
    const float* W_sa = (const float*)d_in[4];
    const float* W_es = (const float*)d_in[5];
    const float* b_es = (const float*)d_in[6];
    const float* W_c1 = (const float*)d_in[7];
    const float* b_c1 = (const float*)d_in[8];
    const float* W_c2 = (const float*)d_in[9];
    const float* b_c2 = (const float*)d_in[10];
    const float* W_n  = (const float*)d_in[11];
    const float* b_n  = (const float*)d_in[12];
    float* out = (float*)d_out;

    const int smem_bytes = (int)sizeof(SMEM);
    cudaFuncSetAttribute(sake_main, cudaFuncAttributeMaxDynamicSharedMemorySize, smem_bytes);

    sake_pre<<<BN, 64>>>(h, W_ew, W_es, W_sa);
    sake_main<<<BN, 256, smem_bytes>>>(h, x, b_ew, W_es, b_es, W_c1, b_c1, W_c2, b_c2, W_n, b_n, out);
}